// round 12
// baseline (speedup 1.0000x reference)
#include <cuda_runtime.h>
#include <cstdint>

// DigitCaps broadcasted batched matvec:
//   u_hat[b,r,c,o] = sum_i W[r,c,o,i] * x[b,r,i] + bias[o]
// B=512, R=1152, C=10, O=16, I=8, fp32.
//
// R10: TMA stores on R8's chassis. R8 (68.2us) was L1-bound with STG.128
// issue (12 cyc/instr, 8.8M cyc chip) the top term; R9 proved TMA bulk
// stores cut L1 but its 64-thread CTAs starved the SM. Here:
//   - block 128, RB=4 (R8 shape), BT=32 (W LDG amortized over 32 b's)
//   - x staged in smem (one 128B line per b, read once chip-wide),
//     broadcast LDS in the loop
//   - results staged per 8-b group (20KB) via STS.128, flushed as 8
//     contiguous 2560B runs with cp.async.bulk.shared->global
//   - smem 48KB -> 4 CTAs = 16 warps/SM
// Lane = bg(4) x c2(2) x o4(4); warp w = r_local.

#define DC_B 512
#define DC_R 1152
#define DC_C 10
#define DC_O 16
#define DC_I 8

#define RB 4      // r rows per block (one per warp)
#define BT 32     // batch elems per block
#define GB 8      // batch elems per flush group
#define NG (BT / GB)

#define SW_FLOATS 5760                 // 4r * 10c * 4(o4) rows of 36 floats
#define SX_FLOATS (BT * 36)            // 1152: 32 b * (32 data + 4 pad)
#define SO_FLOATS (GB * RB * 160)      // 5120 floats = 20480 B stage
#define SMEM_BYTES ((SW_FLOATS + SX_FLOATS + SO_FLOATS) * 4)
#define CHUNK_BYTES (RB * 160 * 4)     // 2560 B contiguous per b

__global__ __launch_bounds__(128, 4)
void digitcaps_kernel(const float* __restrict__ x,
                      const float* __restrict__ W,
                      const float* __restrict__ bias,
                      float* __restrict__ out)
{
    extern __shared__ float smem[];
    float* sW = smem;                          // [g][36], g = (r*10+c)*4+o4
    float* sx = smem + SW_FLOATS;              // [b_local][36]
    float* sO = smem + SW_FLOATS + SX_FLOATS;  // [b_in_group][r_local][160]

    const int tid = threadIdx.x;
    const int r0  = blockIdx.x * RB;
    const int b0  = blockIdx.y * BT;

    // ---- cooperative W load: 4 r rows * 1280 floats = 1280 float4, coalesced ----
    {
        const float4* Wg = reinterpret_cast<const float4*>(
            W + (size_t)r0 * (DC_C * DC_O * DC_I));
#pragma unroll
        for (int q4 = 0; q4 < 10; ++q4) {
            const int q = q4 * 128 + tid;            // float4 index in W tile
            const float4 v = Wg[q];
            const int ih = q & 1;
            const int o  = (q >> 1) & 15;
            const int rc = q >> 5;                   // r_local*10 + c
            const int g  = rc * 4 + (o >> 2);
            *reinterpret_cast<float4*>(sW + g * 36 + (o & 3) * 8 + ih * 4) = v;
        }
    }
    // ---- cooperative x load: 32 b, each b = exactly one 128B line (4r x 8i) ----
    {
#pragma unroll
        for (int it = 0; it < 2; ++it) {
            const int b_i = (tid >> 3) + it * 16;    // 0..31
            const int m   = tid & 7;                 // float4 index within line
            const float4 v = *reinterpret_cast<const float4*>(
                x + ((size_t)(b0 + b_i) * DC_R + r0) * DC_I + m * 4);
            *reinterpret_cast<float4*>(sx + b_i * 36 + m * 4) = v;
        }
    }
    __syncthreads();

    const int lane = tid & 31;
    const int w    = tid >> 5;       // warp id == r_local (0..3)
    const int bg   = lane >> 3;      // 0..3 batch group
    const int c2   = (lane >> 2) & 1;
    const int o4   = lane & 3;

    const float4 bb = *reinterpret_cast<const float4*>(bias + o4 * 4);

#pragma unroll
    for (int g = 0; g < NG; ++g) {
#pragma unroll
        for (int cp = 0; cp < 5; ++cp) {
            const int c = cp * 2 + c2;
            // W row for (r, c, o4): 8 distinct padded rows per warp,
            // stride 36 floats -> conflict-free; bg broadcast dedups.
            const float* wr = sW + ((w * DC_C + c) * 4 + o4) * 36;
            const float4 w0a = *reinterpret_cast<const float4*>(wr + 0);
            const float4 w0b = *reinterpret_cast<const float4*>(wr + 4);
            const float4 w1a = *reinterpret_cast<const float4*>(wr + 8);
            const float4 w1b = *reinterpret_cast<const float4*>(wr + 12);
            const float4 w2a = *reinterpret_cast<const float4*>(wr + 16);
            const float4 w2b = *reinterpret_cast<const float4*>(wr + 20);
            const float4 w3a = *reinterpret_cast<const float4*>(wr + 24);
            const float4 w3b = *reinterpret_cast<const float4*>(wr + 28);

#pragma unroll
            for (int k = 0; k < 2; ++k) {
                const int bl = g * GB + k * 4 + bg;      // block-local b
                // broadcast LDS: 4 distinct 16B addrs per instr (dedup'd)
                const float4 va = *reinterpret_cast<const float4*>(sx + bl * 36 + w * 8);
                const float4 vb = *reinterpret_cast<const float4*>(sx + bl * 36 + w * 8 + 4);

                float4 acc;
                acc.x = fmaf(w0a.x, va.x, fmaf(w0a.y, va.y,
                        fmaf(w0a.z, va.z, fmaf(w0a.w, va.w,
                        fmaf(w0b.x, vb.x, fmaf(w0b.y, vb.y,
                        fmaf(w0b.z, vb.z, fmaf(w0b.w, vb.w, bb.x))))))));
                acc.y = fmaf(w1a.x, va.x, fmaf(w1a.y, va.y,
                        fmaf(w1a.z, va.z, fmaf(w1a.w, va.w,
                        fmaf(w1b.x, vb.x, fmaf(w1b.y, vb.y,
                        fmaf(w1b.z, vb.z, fmaf(w1b.w, vb.w, bb.y))))))));
                acc.z = fmaf(w2a.x, va.x, fmaf(w2a.y, va.y,
                        fmaf(w2a.z, va.z, fmaf(w2a.w, va.w,
                        fmaf(w2b.x, vb.x, fmaf(w2b.y, vb.y,
                        fmaf(w2b.z, vb.z, fmaf(w2b.w, vb.w, bb.z))))))));
                acc.w = fmaf(w3a.x, va.x, fmaf(w3a.y, va.y,
                        fmaf(w3a.z, va.z, fmaf(w3a.w, va.w,
                        fmaf(w3b.x, vb.x, fmaf(w3b.y, vb.y,
                        fmaf(w3b.z, vb.z, fmaf(w3b.w, vb.w, bb.w))))))));

                // STS.128 into stage: per instr 4 x 128B contiguous segments.
                float* sp = sO + (k * 4 + bg) * (RB * 160) + w * 160
                              + c * DC_O + o4 * 4;
                *reinterpret_cast<float4*>(sp) = acc;
            }
        }
        __syncthreads();   // group's STS complete

        // ---- flush group: 8 contiguous 2560B runs via TMA bulk copy ----
        if (tid == 0) {
            asm volatile("fence.proxy.async.shared::cta;" ::: "memory");
            const uint32_t sbase = (uint32_t)__cvta_generic_to_shared(sO);
#pragma unroll
            for (int bi = 0; bi < GB; ++bi) {
                float* dst = out + ((size_t)(b0 + g * GB + bi) * DC_R + r0)
                                 * (DC_C * DC_O);
                asm volatile(
                    "cp.async.bulk.global.shared::cta.bulk_group [%0], [%1], %2;"
                    :: "l"(dst), "r"(sbase + bi * CHUNK_BYTES),
                       "r"((uint32_t)CHUNK_BYTES)
                    : "memory");
            }
            asm volatile("cp.async.bulk.commit_group;" ::: "memory");
            asm volatile("cp.async.bulk.wait_group 0;" ::: "memory");
        }
        __syncthreads();   // stage reusable / safe to exit after last group
    }
}

extern "C" void kernel_launch(void* const* d_in, const int* in_sizes, int n_in,
                              void* d_out, int out_size)
{
    const float* x    = (const float*)d_in[0];  // [B, R, I]
    const float* W    = (const float*)d_in[1];  // [1, R, C, O, I]
    const float* bias = (const float*)d_in[2];  // [O, 1]
    float* out = (float*)d_out;                 // [B, R, C, O, 1]

    cudaFuncSetAttribute(digitcaps_kernel,
                         cudaFuncAttributeMaxDynamicSharedMemorySize, SMEM_BYTES);

    dim3 block(128, 1, 1);
    dim3 grid(DC_R / RB, DC_B / BT, 1);   // (288, 16)
    digitcaps_kernel<<<grid, block, SMEM_BYTES>>>(x, W, bias, out);
}